// round 2
// baseline (speedup 1.0000x reference)
#include <cuda_runtime.h>
#include <cstdint>

#define D   512      // coordinate dimension (nb_coordinates)
#define F   2000     // nb_features
#define NF  16       // filters
#define NB  64       // batch
#define KNN 8        // neighbors
#define TM  64       // i-tile
#define TN  128      // j-tile
#define TK  8        // k-chunk

// Scratch (static device globals; no runtime allocation)
__device__ float g_T[(size_t)NF * F * D];   // [f][i][c], K-contiguous
__device__ float g_sq[NF * F];              // [f][i]
__device__ int   g_idx[F * KNN * NF];       // [(i*8+k)*16 + f]

// ---------------------------------------------------------------------------
// Kernel 1: transpose coordinates (c,i,f) -> T[f][i][c]
// ---------------------------------------------------------------------------
__global__ void k_transpose(const float* __restrict__ coords) {
    __shared__ float s[8][512];
    const int i0     = blockIdx.x * 32;
    const int d_base = blockIdx.y * 64;
    const int tid    = threadIdx.x;          // 512 threads
    const int f      = tid & 15;
    const int il     = tid >> 4;
    const int gi     = i0 + il;

    for (int d0 = d_base; d0 < d_base + 64; d0 += 8) {
        __syncthreads();
        const int col = i0 * NF + tid;
        #pragma unroll
        for (int dd = 0; dd < 8; dd++) {
            s[dd][tid] = (col < F * NF)
                ? coords[(size_t)(d0 + dd) * (F * NF) + col] : 0.f;
        }
        __syncthreads();
        if (gi < F) {
            float t[8];
            #pragma unroll
            for (int dd = 0; dd < 8; dd++) t[dd] = s[dd][il * 16 + f];
            float* dst = g_T + ((size_t)f * F + gi) * D + d0;
            ((float4*)dst)[0] = make_float4(t[0], t[1], t[2], t[3]);
            ((float4*)dst)[1] = make_float4(t[4], t[5], t[6], t[7]);
        }
    }
}

// ---------------------------------------------------------------------------
// Kernel 2: sq[f][i] = sum_c T[f][i][c]^2   (one warp per row)
// ---------------------------------------------------------------------------
__global__ void k_sq() {
    const int row  = blockIdx.x * 8 + (threadIdx.x >> 5);   // row = f*F + i
    const int lane = threadIdx.x & 31;
    if (row >= NF * F) return;
    const float4* p = (const float4*)(g_T + (size_t)row * D);
    float s = 0.f;
    #pragma unroll
    for (int q = 0; q < 4; q++) {
        float4 v = p[lane + q * 32];
        s += v.x * v.x + v.y * v.y + v.z * v.z + v.w * v.w;
    }
    #pragma unroll
    for (int o = 16; o; o >>= 1) s += __shfl_xor_sync(0xFFFFFFFFu, s, o);
    if (lane == 0) g_sq[row] = s;
}

// ---------------------------------------------------------------------------
// Kernel 3: fused Gram + running top-8 per row
//   block = (i-tile of 64, filter f); sweeps all j in tiles of 128.
//   score_j = sq_j - 2 * <x_i, x_j>  (same ordering as clamped distance)
//   key = (ordered_uint(score) << 32) | j  -> ascending sort == jax top_k order
// ---------------------------------------------------------------------------
__global__ void __launch_bounds__(128) k_topk() {
    __shared__ float As[2][TK][68];
    __shared__ float Bs[2][TK][132];
    __shared__ __align__(16) float Ssc[TM][132];
    __shared__ float sqs[TN];

    const int f   = blockIdx.y;
    const int i0  = blockIdx.x * TM;
    const int tid = threadIdx.x;
    const int tx  = tid & 15;       // j-group (8 cols)
    const int ty  = tid >> 4;       // i-group (8 rows)

    const int  arow = tid >> 1;
    const int  acol = (tid & 1) * 4;
    const bool aok  = (i0 + arow) < F;
    const float* Tf    = g_T + (size_t)f * F * D;
    const float* Abase = Tf + (size_t)(aok ? (i0 + arow) : 0) * D + acol;

    const int srow  = tid >> 1;     // selection: 2 threads per row
    const int spart = tid & 1;

    unsigned long long top[KNN];
    #pragma unroll
    for (int k = 0; k < KNN; k++) top[k] = 0xFF800000FFFFFFFFULL;  // score=+inf
    float thr = __int_as_float(0x7F800000);                        // +inf

    for (int jt = 0; jt < F; jt += TN) {
        {
            const int j = jt + tid;
            sqs[tid] = (j < F) ? g_sq[f * F + j] : 3.402823466e38f;
        }
        const int  jrow  = jt + tid;
        const bool bok   = jrow < F;
        const float* Bbase = Tf + (size_t)(bok ? jrow : 0) * D;

        float acc[8][8];
        #pragma unroll
        for (int ii = 0; ii < 8; ii++)
            #pragma unroll
            for (int jj = 0; jj < 8; jj++) acc[ii][jj] = 0.f;

        // prefetch chunk 0
        float4 pa  = make_float4(0.f, 0.f, 0.f, 0.f);
        float4 pb0 = pa, pb1 = pa;
        if (aok) pa  = *(const float4*)(Abase);
        if (bok) { pb0 = *(const float4*)(Bbase); pb1 = *(const float4*)(Bbase + 4); }
        As[0][acol + 0][arow] = pa.x; As[0][acol + 1][arow] = pa.y;
        As[0][acol + 2][arow] = pa.z; As[0][acol + 3][arow] = pa.w;
        Bs[0][0][tid] = pb0.x; Bs[0][1][tid] = pb0.y;
        Bs[0][2][tid] = pb0.z; Bs[0][3][tid] = pb0.w;
        Bs[0][4][tid] = pb1.x; Bs[0][5][tid] = pb1.y;
        Bs[0][6][tid] = pb1.z; Bs[0][7][tid] = pb1.w;
        __syncthreads();

        int buf = 0;
        #pragma unroll 1
        for (int d0 = TK; d0 <= D; d0 += TK) {
            const bool more = (d0 < D);
            if (more) {
                pa = make_float4(0.f, 0.f, 0.f, 0.f); pb0 = pa; pb1 = pa;
                if (aok) pa  = *(const float4*)(Abase + d0);
                if (bok) { pb0 = *(const float4*)(Bbase + d0);
                           pb1 = *(const float4*)(Bbase + d0 + 4); }
            }
            const float* Ab = &As[buf][0][0];
            const float* Bb = &Bs[buf][0][0];
            #pragma unroll
            for (int k = 0; k < TK; k++) {
                float a[8], b[8];
                *(float4*)(a)     = *(const float4*)(Ab + k * 68  + ty * 8);
                *(float4*)(a + 4) = *(const float4*)(Ab + k * 68  + ty * 8 + 4);
                *(float4*)(b)     = *(const float4*)(Bb + k * 132 + tx * 8);
                *(float4*)(b + 4) = *(const float4*)(Bb + k * 132 + tx * 8 + 4);
                #pragma unroll
                for (int ii = 0; ii < 8; ii++)
                    #pragma unroll
                    for (int jj = 0; jj < 8; jj++)
                        acc[ii][jj] = fmaf(a[ii], b[jj], acc[ii][jj]);
            }
            if (more) {
                const int nb = buf ^ 1;
                As[nb][acol + 0][arow] = pa.x; As[nb][acol + 1][arow] = pa.y;
                As[nb][acol + 2][arow] = pa.z; As[nb][acol + 3][arow] = pa.w;
                Bs[nb][0][tid] = pb0.x; Bs[nb][1][tid] = pb0.y;
                Bs[nb][2][tid] = pb0.z; Bs[nb][3][tid] = pb0.w;
                Bs[nb][4][tid] = pb1.x; Bs[nb][5][tid] = pb1.y;
                Bs[nb][6][tid] = pb1.z; Bs[nb][7][tid] = pb1.w;
                __syncthreads();
                buf = nb;
            }
        }

        // stage scores: score = sq_j - 2*acc  (OOB j -> huge, never selected)
        #pragma unroll
        for (int ii = 0; ii < 8; ii++) {
            float sc[8];
            #pragma unroll
            for (int jj = 0; jj < 8; jj++)
                sc[jj] = fmaf(-2.f, acc[ii][jj], sqs[tx * 8 + jj]);
            float* dst = &Ssc[ty * 8 + ii][tx * 8];
            *(float4*)(dst)     = make_float4(sc[0], sc[1], sc[2], sc[3]);
            *(float4*)(dst + 4) = make_float4(sc[4], sc[5], sc[6], sc[7]);
        }
        __syncthreads();

        // running top-8 (2 threads per row, 64 cols each, ascending j)
        for (int c = 0; c < 64; c++) {
            const float s = Ssc[srow][spart * 64 + c];
            if (s <= thr) {
                unsigned int u = __float_as_uint(s);
                u ^= ((unsigned int)(((int)u) >> 31)) | 0x80000000u;
                const unsigned long long key =
                    ((unsigned long long)u << 32) |
                    (unsigned int)(jt + spart * 64 + c);
                if (key < top[7]) {
                    top[7] = key;
                    #pragma unroll
                    for (int q = 7; q > 0; q--) {
                        if (top[q] < top[q - 1]) {
                            unsigned long long t = top[q];
                            top[q] = top[q - 1]; top[q - 1] = t;
                        }
                    }
                    const unsigned int u7 = (unsigned int)(top[7] >> 32);
                    thr = __uint_as_float((u7 & 0x80000000u) ? (u7 & 0x7FFFFFFFu)
                                                             : ~u7);
                }
            }
        }
        __syncthreads();
    }

    // merge the two per-row lists, emit indices
    unsigned long long* M = (unsigned long long*)&Ssc[0][0];
    #pragma unroll
    for (int k = 0; k < KNN; k++) M[tid * 8 + k] = top[k];
    __syncthreads();
    if (spart == 0) {
        const int gi = i0 + srow;
        if (gi < F) {
            int ia = 0, ib = 0;
            #pragma unroll
            for (int k = 0; k < KNN; k++) {
                const unsigned long long ka = M[tid * 8 + ia];
                const unsigned long long kb = M[(tid + 1) * 8 + ib];
                unsigned long long sel;
                if (ka <= kb) { sel = ka; ia++; } else { sel = kb; ib++; }
                g_idx[(gi * KNN + k) * NF + f] =
                    (int)(unsigned int)(sel & 0xFFFFFFFFull);
            }
        }
    }
}

// ---------------------------------------------------------------------------
// Kernel 4: gather  out[b, ik, f] = inputs[b, idx[ik,f], f]
// ---------------------------------------------------------------------------
__global__ void k_gather(const float* __restrict__ inp, float* __restrict__ out) {
    const int ik = blockIdx.x;              // 0 .. F*KNN-1
    const int f  = threadIdx.x & 15;
    const int bq = threadIdx.x >> 4;        // 0..15
    const int j  = g_idx[ik * NF + f];
    #pragma unroll
    for (int p = 0; p < 4; p++) {
        const int b = bq + p * 16;
        out[(size_t)b * (F * KNN * NF) + (size_t)ik * NF + f] =
            inp[(size_t)b * (F * NF) + (size_t)j * NF + f];
    }
}

// ---------------------------------------------------------------------------
extern "C" void kernel_launch(void* const* d_in, const int* in_sizes, int n_in,
                              void* d_out, int out_size) {
    const float* inputs = (const float*)d_in[0];
    const float* coords = (const float*)d_in[1];
    if (n_in >= 2 && in_sizes[0] == D * F * NF) {   // d_in[0] is coordinates
        const float* t = inputs; inputs = coords; coords = t;
    }
    (void)out_size;

    k_transpose<<<dim3((F + 31) / 32, D / 64), 512>>>(coords);
    k_sq<<<(NF * F + 7) / 8, 256>>>();
    k_topk<<<dim3((F + TM - 1) / TM, NF), 128>>>();
    k_gather<<<F * KNN, 256>>>(inputs, (float*)d_out);
}

// round 3
// speedup vs baseline: 2.4368x; 2.4368x over previous
#include <cuda_runtime.h>
#include <cstdint>

#define D   512      // coordinate dimension (nb_coordinates)
#define F   2000     // nb_features
#define NF  16       // filters
#define NB  64       // batch
#define KNN 8        // neighbors
#define TM  64       // i-tile
#define TN  128      // j-tile
#define TK  8        // k-chunk

// Scratch (static device globals; no runtime allocation)
__device__ float g_T[(size_t)NF * F * D];   // [f][i][c], K-contiguous
__device__ float g_sq[NF * F];              // [f][i]
__device__ int   g_idx[F * KNN * NF];       // [(i*8+k)*16 + f]
__device__ float g_dummy_sink;

// f32x2 packed helpers
#define PACKB(dst, fval) \
    asm("mov.b64 %0, {%1, %1};" : "=l"(dst) : "r"(__float_as_uint(fval)))
#define FMA2(d, a, b) \
    asm("fma.rn.f32x2 %0, %1, %2, %0;" : "+l"(d) : "l"(a), "l"(b))

__device__ __forceinline__ float lo32f(unsigned long long v) {
    return __int_as_float((int)(unsigned int)(v & 0xFFFFFFFFull));
}
__device__ __forceinline__ float hi32f(unsigned long long v) {
    return __int_as_float((int)(unsigned int)(v >> 32));
}

// ---------------------------------------------------------------------------
// Kernel 1: transpose coordinates (c,i,f) -> T[f][i][c]
// ---------------------------------------------------------------------------
__global__ void k_transpose(const float* __restrict__ coords) {
    __shared__ float s[8][512];
    const int i0     = blockIdx.x * 32;
    const int d_base = blockIdx.y * 64;
    const int tid    = threadIdx.x;          // 512 threads
    const int f      = tid & 15;
    const int il     = tid >> 4;
    const int gi     = i0 + il;

    for (int d0 = d_base; d0 < d_base + 64; d0 += 8) {
        __syncthreads();
        const int col = i0 * NF + tid;
        #pragma unroll
        for (int dd = 0; dd < 8; dd++) {
            s[dd][tid] = (col < F * NF)
                ? coords[(size_t)(d0 + dd) * (F * NF) + col] : 0.f;
        }
        __syncthreads();
        if (gi < F) {
            float t[8];
            #pragma unroll
            for (int dd = 0; dd < 8; dd++) t[dd] = s[dd][il * 16 + f];
            float* dst = g_T + ((size_t)f * F + gi) * D + d0;
            ((float4*)dst)[0] = make_float4(t[0], t[1], t[2], t[3]);
            ((float4*)dst)[1] = make_float4(t[4], t[5], t[6], t[7]);
        }
    }
}

// ---------------------------------------------------------------------------
// Kernel 2: sq[f][i] = sum_c T[f][i][c]^2   (one warp per row)
// ---------------------------------------------------------------------------
__global__ void k_sq() {
    const int row  = blockIdx.x * 8 + (threadIdx.x >> 5);   // row = f*F + i
    const int lane = threadIdx.x & 31;
    if (row >= NF * F) return;
    const float4* p = (const float4*)(g_T + (size_t)row * D);
    float s = 0.f;
    #pragma unroll
    for (int q = 0; q < 4; q++) {
        float4 v = p[lane + q * 32];
        s += v.x * v.x + v.y * v.y + v.z * v.z + v.w * v.w;
    }
    #pragma unroll
    for (int o = 16; o; o >>= 1) s += __shfl_xor_sync(0xFFFFFFFFu, s, o);
    if (lane == 0) g_sq[row] = s;
}

// dummy launch to align ncu -s capture onto k_topk
__global__ void k_dummy() { if (threadIdx.x == 0) g_dummy_sink = 1.0f; }

// ---------------------------------------------------------------------------
// Kernel 3: fused Gram + running top-8 per row  (f32x2 packed FMA)
//   acc pairs along i: accd[ip][jj] = (dot(row 2ip), dot(row 2ip+1)) packed
// ---------------------------------------------------------------------------
__global__ void __launch_bounds__(128, 4) k_topk() {
    __shared__ float As[2][TK][68];
    __shared__ float Bs[2][TK][2][80];   // split b rows into two 4-float regions
    __shared__ __align__(16) float Ssc[TM][132];
    __shared__ float sqs[TN];

    const int f   = blockIdx.y;
    const int i0  = blockIdx.x * TM;
    const int tid = threadIdx.x;
    const int tx  = tid & 15;       // j-group (8 cols)
    const int ty  = tid >> 4;       // i-group (8 rows)

    const int  arow = tid >> 1;
    const int  acol = (tid & 1) * 4;
    const bool aok  = (i0 + arow) < F;
    const float* Tf    = g_T + (size_t)f * F * D;
    const float* Abase = Tf + (size_t)(aok ? (i0 + arow) : 0) * D + acol;

    // Bs write coords for this thread's j-row
    const int breg = (tid & 7) >> 2;          // region (cols 0-3 vs 4-7)
    const int bidx = (tid >> 3) * 4 + (tid & 3);

    const int srow  = tid >> 1;     // selection: 2 threads per row
    const int spart = tid & 1;

    unsigned long long top[KNN];
    #pragma unroll
    for (int k = 0; k < KNN; k++) top[k] = 0xFF800000FFFFFFFFULL;  // +inf
    float thr = __int_as_float(0x7F800000);                        // +inf

    for (int jt = 0; jt < F; jt += TN) {
        {
            const int j = jt + tid;
            sqs[tid] = (j < F) ? g_sq[f * F + j] : 3.402823466e38f;
        }
        const int  jrow  = jt + tid;
        const bool bok   = jrow < F;
        const float* Bbase = Tf + (size_t)(bok ? jrow : 0) * D;

        unsigned long long accd[4][8];
        #pragma unroll
        for (int ip = 0; ip < 4; ip++)
            #pragma unroll
            for (int jj = 0; jj < 8; jj++) accd[ip][jj] = 0ull;

        // prefetch chunk 0
        float4 pa  = make_float4(0.f, 0.f, 0.f, 0.f);
        float4 pb0 = pa, pb1 = pa;
        if (aok) pa  = *(const float4*)(Abase);
        if (bok) { pb0 = *(const float4*)(Bbase); pb1 = *(const float4*)(Bbase + 4); }
        As[0][acol + 0][arow] = pa.x; As[0][acol + 1][arow] = pa.y;
        As[0][acol + 2][arow] = pa.z; As[0][acol + 3][arow] = pa.w;
        Bs[0][0][breg][bidx] = pb0.x; Bs[0][1][breg][bidx] = pb0.y;
        Bs[0][2][breg][bidx] = pb0.z; Bs[0][3][breg][bidx] = pb0.w;
        Bs[0][4][breg][bidx] = pb1.x; Bs[0][5][breg][bidx] = pb1.y;
        Bs[0][6][breg][bidx] = pb1.z; Bs[0][7][breg][bidx] = pb1.w;
        __syncthreads();

        int buf = 0;
        #pragma unroll 1
        for (int d0 = TK; d0 <= D; d0 += TK) {
            const bool more = (d0 < D);
            if (more) {
                pa = make_float4(0.f, 0.f, 0.f, 0.f); pb0 = pa; pb1 = pa;
                if (aok) pa  = *(const float4*)(Abase + d0);
                if (bok) { pb0 = *(const float4*)(Bbase + d0);
                           pb1 = *(const float4*)(Bbase + d0 + 4); }
            }
            const float* Ab = &As[buf][0][0];
            const float* Bb = &Bs[buf][0][0][0];
            #pragma unroll
            for (int k = 0; k < TK; k++) {
                // a pairs (rows) — free 64-bit pair loads from row-contiguous As
                const ulonglong2* ap =
                    (const ulonglong2*)(Ab + k * 68 + ty * 8);
                ulonglong2 a01_23 = ap[0];
                ulonglong2 a45_67 = ap[1];
                unsigned long long pav[4] =
                    { a01_23.x, a01_23.y, a45_67.x, a45_67.y };
                // b: conflict-free split-region loads + broadcast packs
                float4 b03 = *(const float4*)(Bb + k * 160 + tx * 4);
                float4 b47 = *(const float4*)(Bb + k * 160 + 80 + tx * 4);
                unsigned long long pb[8];
                PACKB(pb[0], b03.x); PACKB(pb[1], b03.y);
                PACKB(pb[2], b03.z); PACKB(pb[3], b03.w);
                PACKB(pb[4], b47.x); PACKB(pb[5], b47.y);
                PACKB(pb[6], b47.z); PACKB(pb[7], b47.w);
                #pragma unroll
                for (int ip = 0; ip < 4; ip++)
                    #pragma unroll
                    for (int jj = 0; jj < 8; jj++)
                        FMA2(accd[ip][jj], pav[ip], pb[jj]);
            }
            if (more) {
                const int nb = buf ^ 1;
                As[nb][acol + 0][arow] = pa.x; As[nb][acol + 1][arow] = pa.y;
                As[nb][acol + 2][arow] = pa.z; As[nb][acol + 3][arow] = pa.w;
                Bs[nb][0][breg][bidx] = pb0.x; Bs[nb][1][breg][bidx] = pb0.y;
                Bs[nb][2][breg][bidx] = pb0.z; Bs[nb][3][breg][bidx] = pb0.w;
                Bs[nb][4][breg][bidx] = pb1.x; Bs[nb][5][breg][bidx] = pb1.y;
                Bs[nb][6][breg][bidx] = pb1.z; Bs[nb][7][breg][bidx] = pb1.w;
                __syncthreads();
                buf = nb;
            }
        }

        // stage scores: score = sq_j - 2*acc
        #pragma unroll
        for (int ip = 0; ip < 4; ip++) {
            float sl[8], sh[8];
            #pragma unroll
            for (int jj = 0; jj < 8; jj++) {
                const float q = sqs[tx * 8 + jj];
                sl[jj] = fmaf(-2.f, lo32f(accd[ip][jj]), q);
                sh[jj] = fmaf(-2.f, hi32f(accd[ip][jj]), q);
            }
            float* d0p = &Ssc[ty * 8 + 2 * ip][tx * 8];
            float* d1p = &Ssc[ty * 8 + 2 * ip + 1][tx * 8];
            *(float4*)(d0p)     = make_float4(sl[0], sl[1], sl[2], sl[3]);
            *(float4*)(d0p + 4) = make_float4(sl[4], sl[5], sl[6], sl[7]);
            *(float4*)(d1p)     = make_float4(sh[0], sh[1], sh[2], sh[3]);
            *(float4*)(d1p + 4) = make_float4(sh[4], sh[5], sh[6], sh[7]);
        }
        __syncthreads();

        // running top-8: unrolled compares -> candidate mask -> sparse inserts
        {
            const float* rowp = &Ssc[srow][spart * 64];
            unsigned long long m = 0;
            #pragma unroll
            for (int q = 0; q < 16; q++) {
                float4 v = ((const float4*)rowp)[q];
                if (v.x <= thr) m |= 1ull << (4 * q + 0);
                if (v.y <= thr) m |= 1ull << (4 * q + 1);
                if (v.z <= thr) m |= 1ull << (4 * q + 2);
                if (v.w <= thr) m |= 1ull << (4 * q + 3);
            }
            while (m) {
                const int c = __ffsll((long long)m) - 1;
                m &= m - 1;
                const float s = rowp[c];
                if (s <= thr) {
                    unsigned int u = __float_as_uint(s);
                    u ^= ((unsigned int)(((int)u) >> 31)) | 0x80000000u;
                    const unsigned long long key =
                        ((unsigned long long)u << 32) |
                        (unsigned int)(jt + spart * 64 + c);
                    if (key < top[7]) {
                        top[7] = key;
                        #pragma unroll
                        for (int q = 7; q > 0; q--) {
                            if (top[q] < top[q - 1]) {
                                unsigned long long t = top[q];
                                top[q] = top[q - 1]; top[q - 1] = t;
                            }
                        }
                        const unsigned int u7 = (unsigned int)(top[7] >> 32);
                        thr = __uint_as_float((u7 & 0x80000000u)
                                              ? (u7 & 0x7FFFFFFFu) : ~u7);
                    }
                }
            }
        }
        __syncthreads();
    }

    // merge the two per-row lists, emit indices
    unsigned long long* M = (unsigned long long*)&Ssc[0][0];
    #pragma unroll
    for (int k = 0; k < KNN; k++) M[tid * 8 + k] = top[k];
    __syncthreads();
    if (spart == 0) {
        const int gi = i0 + srow;
        if (gi < F) {
            int ia = 0, ib = 0;
            #pragma unroll
            for (int k = 0; k < KNN; k++) {
                const unsigned long long ka = M[tid * 8 + ia];
                const unsigned long long kb = M[(tid + 1) * 8 + ib];
                unsigned long long sel;
                if (ka <= kb) { sel = ka; ia++; } else { sel = kb; ib++; }
                g_idx[(gi * KNN + k) * NF + f] =
                    (int)(unsigned int)(sel & 0xFFFFFFFFull);
            }
        }
    }
}

// ---------------------------------------------------------------------------
// Kernel 4: gather  out[b, ik, f] = inputs[b, idx[ik,f], f]
// ---------------------------------------------------------------------------
__global__ void k_gather(const float* __restrict__ inp, float* __restrict__ out) {
    const int ik = blockIdx.x;              // 0 .. F*KNN-1
    const int f  = threadIdx.x & 15;
    const int bq = threadIdx.x >> 4;        // 0..15
    const int j  = g_idx[ik * NF + f];
    #pragma unroll
    for (int p = 0; p < 4; p++) {
        const int b = bq + p * 16;
        out[(size_t)b * (F * KNN * NF) + (size_t)ik * NF + f] =
            inp[(size_t)b * (F * NF) + (size_t)j * NF + f];
    }
}

// ---------------------------------------------------------------------------
extern "C" void kernel_launch(void* const* d_in, const int* in_sizes, int n_in,
                              void* d_out, int out_size) {
    const float* inputs = (const float*)d_in[0];
    const float* coords = (const float*)d_in[1];
    if (n_in >= 2 && in_sizes[0] == D * F * NF) {   // d_in[0] is coordinates
        const float* t = inputs; inputs = coords; coords = t;
    }
    (void)out_size;

    k_transpose<<<dim3((F + 31) / 32, D / 64), 512>>>(coords);
    k_sq<<<(NF * F + 7) / 8, 256>>>();
    k_dummy<<<1, 32>>>();
    k_topk<<<dim3((F + TM - 1) / TM, NF), 128>>>();
    k_gather<<<F * KNN, 256>>>(inputs, (float*)d_out);
}

// round 7
// speedup vs baseline: 3.2117x; 1.3180x over previous
#include <cuda_runtime.h>
#include <cuda_bf16.h>
#include <cstdint>

#define D   512
#define F   2000
#define NF  16
#define KNN 8
#define SL  16

// ---- scratch ----
__device__ float         g_T [(size_t)NF * F * D];
__device__ __nv_bfloat16 g_Tb[(size_t)NF * F * D];
__device__ float         g_sq[NF * F];
__device__ int           g_cand[NF * F * SL];
__device__ int           g_idx [F * KNN * NF];
__device__ float         g_dummy_sink;

// list sentinel: ordered-encoded +inf score, idx -1  (decodes to tv=+inf!)
#define SENT 0xFF800000FFFFFFFFull

// ---- smem layout for k_screen (bytes) ----
#define SM_A   0          // 2 x (128 rows * 80B)  = 20480
#define SM_B   20480      // 2 x (128 rows * 80B)  = 20480
#define SM_SC  40960      // 64 * 132 * 4          = 33792
#define SM_SQ  74752      // 128 * 4               = 512
#define SM_TK  75264      // 256 lists * 16 * 8    = 32768
#define SM_TOTAL 108032
#define BUFB   10240u     // one A/B buffer size

__device__ __forceinline__ uint32_t smem_u32(const void* p) {
    uint32_t a;
    asm("{ .reg .u64 t; cvta.to.shared.u64 t, %1; cvt.u32.u64 %0, t; }"
        : "=r"(a) : "l"(p));
    return a;
}
#define CP16(dst, src) \
    asm volatile("cp.async.cg.shared.global [%0], [%1], 16;" :: "r"(dst), "l"(src))
#define CP_COMMIT() asm volatile("cp.async.commit_group;" ::: "memory")
#define CP_WAIT0()  asm volatile("cp.async.wait_group 0;" ::: "memory")
#define LDSM4(r0, r1, r2, r3, a) \
    asm volatile("ldmatrix.sync.aligned.m8n8.x4.shared.b16 {%0,%1,%2,%3}, [%4];" \
        : "=r"(r0), "=r"(r1), "=r"(r2), "=r"(r3) : "r"(a))

__device__ __forceinline__ void mma16816(float c[4], const uint32_t a[4],
                                         uint32_t b0, uint32_t b1) {
    asm volatile(
        "mma.sync.aligned.m16n8k16.row.col.f32.bf16.bf16.f32 "
        "{%0,%1,%2,%3}, {%4,%5,%6,%7}, {%8,%9}, {%0,%1,%2,%3};"
        : "+f"(c[0]), "+f"(c[1]), "+f"(c[2]), "+f"(c[3])
        : "r"(a[0]), "r"(a[1]), "r"(a[2]), "r"(a[3]), "r"(b0), "r"(b1));
}

// ---------------------------------------------------------------------------
// Kernel 1: transpose coords (c,i,f) -> g_T fp32 + g_Tb bf16, [f][i][c]
// ---------------------------------------------------------------------------
__global__ void k_transpose(const float* __restrict__ coords) {
    __shared__ float s[8][512];
    const int i0 = blockIdx.x * 32, d_base = blockIdx.y * 64;
    const int tid = threadIdx.x;
    const int f = tid & 15, il = tid >> 4, gi = i0 + il;

    for (int d0 = d_base; d0 < d_base + 64; d0 += 8) {
        __syncthreads();
        const int col = i0 * NF + tid;
        #pragma unroll
        for (int dd = 0; dd < 8; dd++)
            s[dd][tid] = (col < F * NF)
                ? coords[(size_t)(d0 + dd) * (F * NF) + col] : 0.f;
        __syncthreads();
        if (gi < F) {
            float t[8];
            #pragma unroll
            for (int dd = 0; dd < 8; dd++) t[dd] = s[dd][il * 16 + f];
            float* dst = g_T + ((size_t)f * F + gi) * D + d0;
            ((float4*)dst)[0] = make_float4(t[0], t[1], t[2], t[3]);
            ((float4*)dst)[1] = make_float4(t[4], t[5], t[6], t[7]);
            __nv_bfloat162 h[4];
            #pragma unroll
            for (int q = 0; q < 4; q++)
                h[q] = __nv_bfloat162(__float2bfloat16_rn(t[2*q]),
                                      __float2bfloat16_rn(t[2*q+1]));
            *(uint4*)(g_Tb + ((size_t)f * F + gi) * D + d0) = *(uint4*)h;
        }
    }
}

// ---------------------------------------------------------------------------
// Kernel 2: sq[f][i]
// ---------------------------------------------------------------------------
__global__ void k_sq() {
    const int row = blockIdx.x * 8 + (threadIdx.x >> 5);
    const int lane = threadIdx.x & 31;
    if (row >= NF * F) return;
    const float4* p = (const float4*)(g_T + (size_t)row * D);
    float s = 0.f;
    #pragma unroll
    for (int q = 0; q < 4; q++) {
        float4 v = p[lane + q * 32];
        s += v.x * v.x + v.y * v.y + v.z * v.z + v.w * v.w;
    }
    #pragma unroll
    for (int o = 16; o; o >>= 1) s += __shfl_xor_sync(0xFFFFFFFFu, s, o);
    if (lane == 0) g_sq[row] = s;
}

__global__ void k_dummy() { if (threadIdx.x == 0) g_dummy_sink = 1.0f; }

// ---------------------------------------------------------------------------
// Kernel 3: bf16 mma.sync screening -> top-16 shortlist per (row, filter)
//   grid (16 i-tiles, 16 filters), 256 threads (8 warps, 2m x 4n).
// ---------------------------------------------------------------------------
__global__ void __launch_bounds__(256, 2) k_screen() {
    extern __shared__ char sm[];
    const uint32_t smb = smem_u32(sm);
    float* scores_sm = (float*)(sm + SM_SC);
    float* sqs_sm    = (float*)(sm + SM_SQ);
    unsigned long long* topk_sm = (unsigned long long*)(sm + SM_TK);

    const int tid = threadIdx.x, lane = tid & 31, wid = tid >> 5;
    const int wm = wid & 1, wn = wid >> 1;
    const int f = blockIdx.y, i0 = blockIdx.x * 128;
    const __nv_bfloat16* Tbf = g_Tb + (size_t)f * F * D;

    for (int k = tid; k < 256 * SL; k += 256)
        topk_sm[k] = SENT;                       // decodes to threshold +inf
    float thrv[2] = { __int_as_float(0x7F800000), __int_as_float(0x7F800000) };

    // cp.async coords: thread t covers row = t>>1, elements lq*16 .. lq*16+15
    const int lrow = tid >> 1, lq = tid & 1;
    const int arow_g = min(i0 + lrow, F - 1);
    const uint32_t st_off = (uint32_t)lrow * 80u + (uint32_t)lq * 32u;

    // ldmatrix bases (pad-40 rows: 80 bytes)
    const uint32_t lm_col = (lane & 16) ? 16u : 0u;
    const uint32_t aBase = smb + SM_A + (uint32_t)(wm * 64 + (lane & 15)) * 80u + lm_col;
    const uint32_t bBase = smb + SM_B + (uint32_t)(wn * 32 + (lane & 15)) * 80u + lm_col;

    for (int jt = 0; jt < 16; jt++) {
        if (tid < 128) {
            const int j = jt * 128 + tid;
            sqs_sm[tid] = (j < F) ? g_sq[f * F + j] : __int_as_float(0x7F800000);
        }
        const int jrow_g = min(jt * 128 + lrow, F - 1);
        const __nv_bfloat16* asrc0 = Tbf + (size_t)arow_g * D + lq * 16;
        const __nv_bfloat16* bsrc0 = Tbf + (size_t)jrow_g * D + lq * 16;

        float c[4][4][4];
        #pragma unroll
        for (int mt = 0; mt < 4; mt++)
            #pragma unroll
            for (int nt = 0; nt < 4; nt++)
                #pragma unroll
                for (int e = 0; e < 4; e++) c[mt][nt][e] = 0.f;

        // prefetch chunk 0 (full 64B per row: 2 cp.async per matrix per thread)
        CP16(smb + SM_A + st_off,       asrc0);
        CP16(smb + SM_A + st_off + 16u, asrc0 + 8);
        CP16(smb + SM_B + st_off,       bsrc0);
        CP16(smb + SM_B + st_off + 16u, bsrc0 + 8);
        CP_COMMIT();
        CP_WAIT0();
        __syncthreads();

        #pragma unroll 1
        for (int kc = 0; kc < 16; kc++) {
            const uint32_t cb = (uint32_t)(kc & 1) * BUFB;
            if (kc < 15) {
                const uint32_t nb = (uint32_t)((kc + 1) & 1) * BUFB;
                const int ko = (kc + 1) * 32;
                CP16(smb + SM_A + nb + st_off,       asrc0 + ko);
                CP16(smb + SM_A + nb + st_off + 16u, asrc0 + ko + 8);
                CP16(smb + SM_B + nb + st_off,       bsrc0 + ko);
                CP16(smb + SM_B + nb + st_off + 16u, bsrc0 + ko + 8);
                CP_COMMIT();
            }
            #pragma unroll
            for (int ks = 0; ks < 2; ks++) {
                uint32_t a[4][4], b[4][2], t0, t1, t2, t3;
                #pragma unroll
                for (int mt = 0; mt < 4; mt++)
                    LDSM4(a[mt][0], a[mt][1], a[mt][2], a[mt][3],
                          aBase + cb + (uint32_t)mt * 1280u + (uint32_t)ks * 32u);
                #pragma unroll
                for (int p = 0; p < 2; p++) {
                    LDSM4(t0, t1, t2, t3,
                          bBase + cb + (uint32_t)p * 1280u + (uint32_t)ks * 32u);
                    b[2*p][0] = t0; b[2*p][1] = t2;
                    b[2*p+1][0] = t1; b[2*p+1][1] = t3;
                }
                #pragma unroll
                for (int mt = 0; mt < 4; mt++)
                    #pragma unroll
                    for (int nt = 0; nt < 4; nt++)
                        mma16816(c[mt][nt], a[mt], b[nt][0], b[nt][1]);
            }
            if (kc < 15) { CP_WAIT0(); __syncthreads(); }
        }

        // epilogue in two row-halves
        #pragma unroll 1
        for (int h = 0; h < 2; h++) {
            __syncthreads();
            if (wm == h) {
                #pragma unroll
                for (int mt = 0; mt < 4; mt++) {
                    const int r0 = mt * 16 + (lane >> 2);
                    #pragma unroll
                    for (int nt = 0; nt < 4; nt++) {
                        const int col = wn * 32 + nt * 8 + 2 * (lane & 3);
                        const float q0 = sqs_sm[col], q1 = sqs_sm[col + 1];
                        float2 v0, v1;
                        v0.x = fmaf(-2.f, c[mt][nt][0], q0);
                        v0.y = fmaf(-2.f, c[mt][nt][1], q1);
                        v1.x = fmaf(-2.f, c[mt][nt][2], q0);
                        v1.y = fmaf(-2.f, c[mt][nt][3], q1);
                        *(float2*)(scores_sm + r0 * 132 + col)       = v0;
                        *(float2*)(scores_sm + (r0 + 8) * 132 + col) = v1;
                    }
                }
            }
            __syncthreads();
            if (tid < 128) {
                const int row_l = tid >> 1, part = tid & 1;
                unsigned long long* L = topk_sm + (size_t)(h * 128 + tid) * SL;
                float tv = thrv[h];
                const float4* rp =
                    (const float4*)(scores_sm + row_l * 132 + part * 64);
                const int jb = jt * 128 + part * 64;
                #pragma unroll 1
                for (int q = 0; q < 16; q++) {
                    const float4 v = rp[q];
                    const float ss[4] = { v.x, v.y, v.z, v.w };
                    #pragma unroll
                    for (int e = 0; e < 4; e++) {
                        const float s = ss[e];
                        if (s <= tv) {
                            unsigned u = __float_as_uint(s);
                            u ^= ((unsigned)(((int)u) >> 31)) | 0x80000000u;
                            const unsigned long long key =
                                ((unsigned long long)u << 32)
                                | (unsigned)(jb + q * 4 + e);
                            if (key < L[SL - 1]) {
                                int pos = SL - 1;
                                #pragma unroll 1
                                while (pos > 0 && key < L[pos - 1]) {
                                    L[pos] = L[pos - 1]; pos--;
                                }
                                L[pos] = key;
                                const unsigned ut = (unsigned)(L[SL - 1] >> 32);
                                tv = __uint_as_float((ut & 0x80000000u)
                                        ? (ut & 0x7FFFFFFFu) : ~ut);
                            }
                        }
                    }
                }
                thrv[h] = tv;
            }
        }
        __syncthreads();
    }

    // merge the two per-row lists -> top-16 shortlist
    if (tid < 128) {
        const int gi = i0 + tid;
        if (gi < F) {
            const int h = tid >> 6, rl = tid & 63;
            const unsigned long long* L0 =
                topk_sm + (size_t)(h * 128 + rl * 2) * SL;
            const unsigned long long* L1 = L0 + SL;
            int ia = 0, ib = 0;
            const int base = (f * F + gi) * SL;
            #pragma unroll
            for (int k = 0; k < SL; k++) {
                const unsigned long long ka =
                    (ia < SL) ? L0[ia] : 0xFFFFFFFFFFFFFFFFull;
                const unsigned long long kb =
                    (ib < SL) ? L1[ib] : 0xFFFFFFFFFFFFFFFFull;
                unsigned long long sel;
                if (ka <= kb) { sel = ka; ia++; } else { sel = kb; ib++; }
                g_cand[base + k] = (int)(unsigned)(sel & 0xFFFFFFFFull);
            }
        }
    }
}

// ---------------------------------------------------------------------------
// Kernel 4: exact fp32 rescore of the shortlist; emit top-8 indices
// ---------------------------------------------------------------------------
__global__ void __launch_bounds__(256) k_rescore() {
    const int wid = threadIdx.x >> 5, lane = threadIdx.x & 31;
    const int row = blockIdx.x * 8 + wid;
    if (row >= NF * F) return;
    const int f = row / F, i = row - f * F;
    const float* xi = g_T + (size_t)row * D;
    float4 xa[4];
    #pragma unroll
    for (int q = 0; q < 4; q++) xa[q] = *(const float4*)(xi + lane * 16 + q * 4);

    unsigned long long keys[SL];
    #pragma unroll 1
    for (int c = 0; c < SL; c++) {
        const int j = g_cand[row * SL + c];
        const float* xj = g_T + ((size_t)f * F + j) * D;
        float p = 0.f;
        #pragma unroll
        for (int q = 0; q < 4; q++) {
            float4 v = *(const float4*)(xj + lane * 16 + q * 4);
            p = fmaf(xa[q].x, v.x, p); p = fmaf(xa[q].y, v.y, p);
            p = fmaf(xa[q].z, v.z, p); p = fmaf(xa[q].w, v.w, p);
        }
        #pragma unroll
        for (int o = 16; o; o >>= 1) p += __shfl_xor_sync(0xFFFFFFFFu, p, o);
        const float s = fmaf(-2.f, p, g_sq[f * F + j]);
        unsigned u = __float_as_uint(s);
        u ^= ((unsigned)(((int)u) >> 31)) | 0x80000000u;
        keys[c] = ((unsigned long long)u << 32) | (unsigned)j;
    }
    if (lane == 0) {
        #pragma unroll
        for (int k = 0; k < KNN; k++) {
            int m = k;
            #pragma unroll
            for (int c = k + 1; c < SL; c++) if (keys[c] < keys[m]) m = c;
            const unsigned long long tk = keys[m];
            keys[m] = keys[k]; keys[k] = tk;
            g_idx[((size_t)i * KNN + k) * NF + f] =
                (int)(unsigned)(tk & 0xFFFFFFFFull);
        }
    }
}

// ---------------------------------------------------------------------------
// Kernel 5: gather
// ---------------------------------------------------------------------------
__global__ void k_gather(const float* __restrict__ inp, float* __restrict__ out) {
    const int ik = blockIdx.x;
    const int f  = threadIdx.x & 15;
    const int bq = threadIdx.x >> 4;
    const int j  = g_idx[ik * NF + f];
    #pragma unroll
    for (int p = 0; p < 4; p++) {
        const int b = bq + p * 16;
        out[(size_t)b * (F * KNN * NF) + (size_t)ik * NF + f] =
            inp[(size_t)b * (F * NF) + (size_t)j * NF + f];
    }
}

// ---------------------------------------------------------------------------
extern "C" void kernel_launch(void* const* d_in, const int* in_sizes, int n_in,
                              void* d_out, int out_size) {
    const float* inputs = (const float*)d_in[0];
    const float* coords = (const float*)d_in[1];
    if (n_in >= 2 && in_sizes[0] == D * F * NF) {
        const float* t = inputs; inputs = coords; coords = t;
    }
    (void)out_size;

    static bool attr_done = false;
    if (!attr_done) {
        cudaFuncSetAttribute(k_screen,
            cudaFuncAttributeMaxDynamicSharedMemorySize, SM_TOTAL);
        attr_done = true;
    }

    k_transpose<<<dim3((F + 31) / 32, D / 64), 512>>>(coords);
    k_sq<<<(NF * F + 7) / 8, 256>>>();
    k_dummy<<<1, 32>>>();
    k_screen<<<dim3(16, NF), 256, SM_TOTAL>>>();
    k_rescore<<<(NF * F + 7) / 8, 256>>>();
    k_gather<<<F * KNN, 256>>>(inputs, (float*)d_out);
}

// round 8
// speedup vs baseline: 4.4543x; 1.3869x over previous
#include <cuda_runtime.h>
#include <cuda_bf16.h>
#include <cstdint>

#define D   512
#define F   2000
#define NF  16
#define KNN 8
#define SL  16

// ---- scratch ----
__device__ float         g_T [(size_t)NF * F * D];
__device__ __nv_bfloat16 g_Tb[(size_t)NF * F * D];
__device__ float         g_sq[NF * F];
__device__ int           g_cand[NF * F * SL];
__device__ int           g_idx [F * KNN * NF];
__device__ float         g_dummy_sink;

// sentinel: ordered-encoded +inf score, idx -1
#define SENT 0xFF800000FFFFFFFFull
#define FULLM 0xFFFFFFFFu

// ---- smem layout for k_screen (bytes): 3-stage A/B ring ----
#define SM_A    0         // 3 x 10240 = 30720
#define SM_B    30720     // 3 x 10240 = 30720
#define SM_SC   61440     // 64 x 132 x 4 = 33792
#define SM_SQ   95232     // 128 x 4 = 512
#define SM_LIST 95744     // 128 rows x 16 x 8 = 16384
#define SM_TOTAL 112128
#define BUFB    10240u

__device__ __forceinline__ uint32_t smem_u32(const void* p) {
    uint32_t a;
    asm("{ .reg .u64 t; cvta.to.shared.u64 t, %1; cvt.u32.u64 %0, t; }"
        : "=r"(a) : "l"(p));
    return a;
}
#define CP16(dst, src) \
    asm volatile("cp.async.cg.shared.global [%0], [%1], 16;" :: "r"(dst), "l"(src))
#define CP_COMMIT() asm volatile("cp.async.commit_group;" ::: "memory")
#define CP_WAIT0()  asm volatile("cp.async.wait_group 0;" ::: "memory")
#define CP_WAIT1()  asm volatile("cp.async.wait_group 1;" ::: "memory")
#define LDSM4(r0, r1, r2, r3, a) \
    asm volatile("ldmatrix.sync.aligned.m8n8.x4.shared.b16 {%0,%1,%2,%3}, [%4];" \
        : "=r"(r0), "=r"(r1), "=r"(r2), "=r"(r3) : "r"(a))

__device__ __forceinline__ void mma16816(float c[4], const uint32_t a[4],
                                         uint32_t b0, uint32_t b1) {
    asm volatile(
        "mma.sync.aligned.m16n8k16.row.col.f32.bf16.bf16.f32 "
        "{%0,%1,%2,%3}, {%4,%5,%6,%7}, {%8,%9}, {%0,%1,%2,%3};"
        : "+f"(c[0]), "+f"(c[1]), "+f"(c[2]), "+f"(c[3])
        : "r"(a[0]), "r"(a[1]), "r"(a[2]), "r"(a[3]), "r"(b0), "r"(b1));
}

__device__ __forceinline__ float dec_thr(unsigned hi) {
    return __uint_as_float((hi & 0x80000000u) ? (hi & 0x7FFFFFFFu) : ~hi);
}

// ---------------------------------------------------------------------------
// Kernel 1: transpose coords (c,i,f) -> g_T fp32 + g_Tb bf16, [f][i][c]
// ---------------------------------------------------------------------------
__global__ void k_transpose(const float* __restrict__ coords) {
    __shared__ float s[8][512];
    const int i0 = blockIdx.x * 32, d_base = blockIdx.y * 64;
    const int tid = threadIdx.x;
    const int f = tid & 15, il = tid >> 4, gi = i0 + il;

    for (int d0 = d_base; d0 < d_base + 64; d0 += 8) {
        __syncthreads();
        const int col = i0 * NF + tid;
        #pragma unroll
        for (int dd = 0; dd < 8; dd++)
            s[dd][tid] = (col < F * NF)
                ? coords[(size_t)(d0 + dd) * (F * NF) + col] : 0.f;
        __syncthreads();
        if (gi < F) {
            float t[8];
            #pragma unroll
            for (int dd = 0; dd < 8; dd++) t[dd] = s[dd][il * 16 + f];
            float* dst = g_T + ((size_t)f * F + gi) * D + d0;
            ((float4*)dst)[0] = make_float4(t[0], t[1], t[2], t[3]);
            ((float4*)dst)[1] = make_float4(t[4], t[5], t[6], t[7]);
            __nv_bfloat162 h[4];
            #pragma unroll
            for (int q = 0; q < 4; q++)
                h[q] = __nv_bfloat162(__float2bfloat16_rn(t[2*q]),
                                      __float2bfloat16_rn(t[2*q+1]));
            *(uint4*)(g_Tb + ((size_t)f * F + gi) * D + d0) = *(uint4*)h;
        }
    }
}

// ---------------------------------------------------------------------------
// Kernel 2: sq[f][i]
// ---------------------------------------------------------------------------
__global__ void k_sq() {
    const int row = blockIdx.x * 8 + (threadIdx.x >> 5);
    const int lane = threadIdx.x & 31;
    if (row >= NF * F) return;
    const float4* p = (const float4*)(g_T + (size_t)row * D);
    float s = 0.f;
    #pragma unroll
    for (int q = 0; q < 4; q++) {
        float4 v = p[lane + q * 32];
        s += v.x * v.x + v.y * v.y + v.z * v.z + v.w * v.w;
    }
    #pragma unroll
    for (int o = 16; o; o >>= 1) s += __shfl_xor_sync(FULLM, s, o);
    if (lane == 0) g_sq[row] = s;
}

__global__ void k_dummy() { if (threadIdx.x == 0) g_dummy_sink = 1.0f; }

// ---------------------------------------------------------------------------
// Kernel 3: bf16 mma.sync screening -> top-16 shortlist per (row, filter)
//   grid (16 i-tiles, 16 filters), 256 threads (8 warps, 2m x 4n).
//   Selection: warp-cooperative list, one element per lane (lanes 0-15).
// ---------------------------------------------------------------------------
__global__ void __launch_bounds__(256, 2) k_screen() {
    extern __shared__ char sm[];
    const uint32_t smb = smem_u32(sm);
    float* scores_sm = (float*)(sm + SM_SC);
    float* sqs_sm    = (float*)(sm + SM_SQ);
    unsigned long long* list_sm = (unsigned long long*)(sm + SM_LIST);

    const int tid = threadIdx.x, lane = tid & 31, wid = tid >> 5;
    const int wm = wid & 1, wn = wid >> 1;
    const int f = blockIdx.y, i0 = blockIdx.x * 128;
    const __nv_bfloat16* Tbf = g_Tb + (size_t)f * F * D;

    for (int k = tid; k < 128 * SL; k += 256) list_sm[k] = SENT;

    // cp.async coords: thread t covers row = t>>1, elements (t&1)*16 .. +15
    const int lrow = tid >> 1, lq = tid & 1;
    const int arow_g = min(i0 + lrow, F - 1);
    const uint32_t st_off = (uint32_t)lrow * 80u + (uint32_t)lq * 32u;

    // ldmatrix bases (pad rows: 80 bytes)
    const uint32_t lm_col = (lane & 16) ? 16u : 0u;
    const uint32_t aBase = smb + SM_A + (uint32_t)(wm * 64 + (lane & 15)) * 80u + lm_col;
    const uint32_t bBase = smb + SM_B + (uint32_t)(wn * 32 + (lane & 15)) * 80u + lm_col;

    const __nv_bfloat16* asrc0 = Tbf + (size_t)arow_g * D + lq * 16;

    for (int jt = 0; jt < 16; jt++) {
        if (tid < 128) {
            const int j = jt * 128 + tid;
            sqs_sm[tid] = (j < F) ? g_sq[f * F + j] : __int_as_float(0x7F800000);
        }
        const int jrow_g = min(jt * 128 + lrow, F - 1);
        const __nv_bfloat16* bsrc0 = Tbf + (size_t)jrow_g * D + lq * 16;

        float c[4][4][4];
        #pragma unroll
        for (int mt = 0; mt < 4; mt++)
            #pragma unroll
            for (int nt = 0; nt < 4; nt++)
                #pragma unroll
                for (int e = 0; e < 4; e++) c[mt][nt][e] = 0.f;

        // prologue: prefetch chunks 0 and 1
        #pragma unroll
        for (int pc = 0; pc < 2; pc++) {
            const uint32_t nb = (uint32_t)pc * BUFB;
            const int ko = pc * 32;
            CP16(smb + SM_A + nb + st_off,       asrc0 + ko);
            CP16(smb + SM_A + nb + st_off + 16u, asrc0 + ko + 8);
            CP16(smb + SM_B + nb + st_off,       bsrc0 + ko);
            CP16(smb + SM_B + nb + st_off + 16u, bsrc0 + ko + 8);
            CP_COMMIT();
        }

        #pragma unroll 1
        for (int kc = 0; kc < 16; kc++) {
            if (kc < 15) CP_WAIT1(); else CP_WAIT0();
            __syncthreads();
            if (kc + 2 < 16) {
                const uint32_t nb = (uint32_t)((kc + 2) % 3) * BUFB;
                const int ko = (kc + 2) * 32;
                CP16(smb + SM_A + nb + st_off,       asrc0 + ko);
                CP16(smb + SM_A + nb + st_off + 16u, asrc0 + ko + 8);
                CP16(smb + SM_B + nb + st_off,       bsrc0 + ko);
                CP16(smb + SM_B + nb + st_off + 16u, bsrc0 + ko + 8);
                CP_COMMIT();
            }
            const uint32_t cb = (uint32_t)(kc % 3) * BUFB;
            #pragma unroll
            for (int ks = 0; ks < 2; ks++) {
                uint32_t a[4][4], b[4][2], t0, t1, t2, t3;
                #pragma unroll
                for (int mt = 0; mt < 4; mt++)
                    LDSM4(a[mt][0], a[mt][1], a[mt][2], a[mt][3],
                          aBase + cb + (uint32_t)mt * 1280u + (uint32_t)ks * 32u);
                #pragma unroll
                for (int p = 0; p < 2; p++) {
                    LDSM4(t0, t1, t2, t3,
                          bBase + cb + (uint32_t)p * 1280u + (uint32_t)ks * 32u);
                    b[2*p][0] = t0; b[2*p][1] = t2;
                    b[2*p+1][0] = t1; b[2*p+1][1] = t3;
                }
                #pragma unroll
                for (int mt = 0; mt < 4; mt++)
                    #pragma unroll
                    for (int nt = 0; nt < 4; nt++)
                        mma16816(c[mt][nt], a[mt], b[nt][0], b[nt][1]);
            }
        }

        // epilogue: two row-halves; stage scores, then warp-cooperative top-16
        const int jb = jt * 128;
        #pragma unroll 1
        for (int h = 0; h < 2; h++) {
            __syncthreads();
            if (wm == h) {
                #pragma unroll
                for (int mt = 0; mt < 4; mt++) {
                    const int r0 = mt * 16 + (lane >> 2);
                    #pragma unroll
                    for (int nt = 0; nt < 4; nt++) {
                        const int col = wn * 32 + nt * 8 + 2 * (lane & 3);
                        const float q0 = sqs_sm[col], q1 = sqs_sm[col + 1];
                        float2 v0, v1;
                        v0.x = fmaf(-2.f, c[mt][nt][0], q0);
                        v0.y = fmaf(-2.f, c[mt][nt][1], q1);
                        v1.x = fmaf(-2.f, c[mt][nt][2], q0);
                        v1.y = fmaf(-2.f, c[mt][nt][3], q1);
                        *(float2*)(scores_sm + r0 * 132 + col)       = v0;
                        *(float2*)(scores_sm + (r0 + 8) * 132 + col) = v1;
                    }
                }
            }
            __syncthreads();
            // each warp: 8 rows of the 64 staged
            #pragma unroll 1
            for (int rr = 0; rr < 8; rr++) {
                const int rl = wid * 8 + rr;          // local row 0..63
                const int grow = h * 64 + rl;         // global row 0..127
                unsigned long long Lv = SENT;
                if (lane < 16) Lv = list_sm[grow * SL + lane];
                unsigned long long L15 = __shfl_sync(FULLM, Lv, 15);
                float thr = dec_thr((unsigned)(L15 >> 32));

                const float4 v = *(const float4*)(scores_sm + rl * 132 + lane * 4);
                unsigned pend = (v.x <= thr ? 1u : 0u) | (v.y <= thr ? 2u : 0u)
                              | (v.z <= thr ? 4u : 0u) | (v.w <= thr ? 8u : 0u);
                while (true) {
                    const unsigned any = __ballot_sync(FULLM, pend != 0u);
                    if (!any) break;
                    const int src = __ffs(any) - 1;
                    const unsigned spend = __shfl_sync(FULLM, pend, src);
                    const int e = __ffs(spend) - 1;
                    if (lane == src) pend &= pend - 1;
                    const float vx = (e == 0) ? v.x : (e == 1) ? v.y
                                   : (e == 2) ? v.z : v.w;
                    const float sv = __shfl_sync(FULLM, vx, src);
                    unsigned u = __float_as_uint(sv);
                    u ^= ((unsigned)(((int)u) >> 31)) | 0x80000000u;
                    const unsigned long long key =
                        ((unsigned long long)u << 32)
                        | (unsigned)(jb + src * 4 + e);
                    if (key < L15) {
                        const unsigned bal =
                            __ballot_sync(FULLM, (lane < 16) && (Lv < key));
                        const int pos = __popc(bal);
                        const unsigned long long up = __shfl_up_sync(FULLM, Lv, 1);
                        if (lane < 16)
                            Lv = (lane < pos) ? Lv : ((lane == pos) ? key : up);
                        L15 = __shfl_sync(FULLM, Lv, 15);
                        thr = dec_thr((unsigned)(L15 >> 32));
                        pend &= (v.x <= thr ? 1u : 0u) | (v.y <= thr ? 2u : 0u)
                              | (v.z <= thr ? 4u : 0u) | (v.w <= thr ? 8u : 0u);
                    }
                }
                if (lane < 16) list_sm[grow * SL + lane] = Lv;
            }
        }
        __syncthreads();
    }

    // write shortlists (lists are already sorted ascending)
    for (int idx = tid; idx < 128 * SL; idx += 256) {
        const int row = idx >> 4, k = idx & 15;
        const int gi = i0 + row;
        if (gi < F)
            g_cand[(f * F + gi) * SL + k] =
                (int)(unsigned)(list_sm[row * SL + k] & 0xFFFFFFFFull);
    }
}

// ---------------------------------------------------------------------------
// Kernel 4: exact fp32 rescore of the shortlist; emit top-8 indices
// ---------------------------------------------------------------------------
__global__ void __launch_bounds__(256) k_rescore() {
    const int wid = threadIdx.x >> 5, lane = threadIdx.x & 31;
    const int row = blockIdx.x * 8 + wid;
    if (row >= NF * F) return;
    const int f = row / F, i = row - f * F;
    const float* xi = g_T + (size_t)row * D;
    float4 xa[4];
    #pragma unroll
    for (int q = 0; q < 4; q++) xa[q] = *(const float4*)(xi + lane * 16 + q * 4);

    unsigned long long keys[SL];
    #pragma unroll 1
    for (int c = 0; c < SL; c += 2) {
        const int j0 = g_cand[row * SL + c];
        const int j1 = g_cand[row * SL + c + 1];
        const float* x0 = g_T + ((size_t)f * F + j0) * D;
        const float* x1 = g_T + ((size_t)f * F + j1) * D;
        float p0 = 0.f, p1 = 0.f;
        #pragma unroll
        for (int q = 0; q < 4; q++) {
            float4 a = xa[q];
            float4 v0 = *(const float4*)(x0 + lane * 16 + q * 4);
            float4 v1 = *(const float4*)(x1 + lane * 16 + q * 4);
            p0 = fmaf(a.x, v0.x, p0); p1 = fmaf(a.x, v1.x, p1);
            p0 = fmaf(a.y, v0.y, p0); p1 = fmaf(a.y, v1.y, p1);
            p0 = fmaf(a.z, v0.z, p0); p1 = fmaf(a.z, v1.z, p1);
            p0 = fmaf(a.w, v0.w, p0); p1 = fmaf(a.w, v1.w, p1);
        }
        #pragma unroll
        for (int o = 16; o; o >>= 1) {
            p0 += __shfl_xor_sync(FULLM, p0, o);
            p1 += __shfl_xor_sync(FULLM, p1, o);
        }
        const float s0 = fmaf(-2.f, p0, g_sq[f * F + j0]);
        const float s1 = fmaf(-2.f, p1, g_sq[f * F + j1]);
        unsigned u0 = __float_as_uint(s0);
        u0 ^= ((unsigned)(((int)u0) >> 31)) | 0x80000000u;
        unsigned u1 = __float_as_uint(s1);
        u1 ^= ((unsigned)(((int)u1) >> 31)) | 0x80000000u;
        keys[c]     = ((unsigned long long)u0 << 32) | (unsigned)j0;
        keys[c + 1] = ((unsigned long long)u1 << 32) | (unsigned)j1;
    }
    if (lane == 0) {
        #pragma unroll
        for (int k = 0; k < KNN; k++) {
            int m = k;
            #pragma unroll
            for (int c = k + 1; c < SL; c++) if (keys[c] < keys[m]) m = c;
            const unsigned long long tk = keys[m];
            keys[m] = keys[k]; keys[k] = tk;
            g_idx[((size_t)i * KNN + k) * NF + f] =
                (int)(unsigned)(tk & 0xFFFFFFFFull);
        }
    }
}

// ---------------------------------------------------------------------------
// Kernel 5: gather — warp covers 32 contiguous (ik,f) pairs -> 128B stores
// ---------------------------------------------------------------------------
__global__ void k_gather(const float* __restrict__ inp, float* __restrict__ out) {
    const int wid = threadIdx.x >> 5, lane = threadIdx.x & 31;
    const int ik = blockIdx.x * 16 + wid * 2 + (lane >> 4);
    const int f  = lane & 15;
    const int j  = g_idx[ik * NF + f];
    const float* src = inp + (size_t)j * NF + f;
    float* dst = out + (size_t)ik * NF + f;
    #pragma unroll 8
    for (int b = 0; b < 64; b++)
        dst[(size_t)b * (F * KNN * NF)] = src[(size_t)b * (F * NF)];
}

// ---------------------------------------------------------------------------
extern "C" void kernel_launch(void* const* d_in, const int* in_sizes, int n_in,
                              void* d_out, int out_size) {
    const float* inputs = (const float*)d_in[0];
    const float* coords = (const float*)d_in[1];
    if (n_in >= 2 && in_sizes[0] == D * F * NF) {
        const float* t = inputs; inputs = coords; coords = t;
    }
    (void)out_size;

    static bool attr_done = false;
    if (!attr_done) {
        cudaFuncSetAttribute(k_screen,
            cudaFuncAttributeMaxDynamicSharedMemorySize, SM_TOTAL);
        attr_done = true;
    }

    k_transpose<<<dim3((F + 31) / 32, D / 64), 512>>>(coords);
    k_sq<<<(NF * F + 7) / 8, 256>>>();
    k_dummy<<<1, 32>>>();
    k_screen<<<dim3(16, NF), 256, SM_TOTAL>>>();
    k_rescore<<<(NF * F + 7) / 8, 256>>>();
    k_gather<<<F * KNN / 16, 256>>>(inputs, (float*)d_out);
}

// round 9
// speedup vs baseline: 5.1320x; 1.1522x over previous
#include <cuda_runtime.h>
#include <cuda_bf16.h>
#include <cstdint>

#define D   512
#define F   2000
#define NF  16
#define KNN 8
#define SL  16
#define FP  2048      // padded rows/cols of score buffer

// ---- scratch ----
__device__ float         g_T [(size_t)NF * F * D];
__device__ __nv_bfloat16 g_Tb[(size_t)NF * F * D];
__device__ float         g_sq[NF * F];
__device__ float         g_scores[(size_t)NF * FP * FP];   // raw dot products
__device__ int           g_cand[NF * F * SL];
__device__ int           g_idx [F * KNN * NF];
__device__ float         g_dummy_sink;

#define SENT 0xFF800000FFFFFFFFull
#define FULLM 0xFFFFFFFFu

// ---- smem for k_gemm: 3-stage A/B ring only ----
#define SM_A    0         // 3 x 10240
#define SM_B    30720     // 3 x 10240
#define SM_TOTAL 61440
#define BUFB    10240u

__device__ __forceinline__ uint32_t smem_u32(const void* p) {
    uint32_t a;
    asm("{ .reg .u64 t; cvta.to.shared.u64 t, %1; cvt.u32.u64 %0, t; }"
        : "=r"(a) : "l"(p));
    return a;
}
#define CP16(dst, src) \
    asm volatile("cp.async.cg.shared.global [%0], [%1], 16;" :: "r"(dst), "l"(src))
#define CP_COMMIT() asm volatile("cp.async.commit_group;" ::: "memory")
#define CP_WAIT0()  asm volatile("cp.async.wait_group 0;" ::: "memory")
#define CP_WAIT1()  asm volatile("cp.async.wait_group 1;" ::: "memory")
#define LDSM4(r0, r1, r2, r3, a) \
    asm volatile("ldmatrix.sync.aligned.m8n8.x4.shared.b16 {%0,%1,%2,%3}, [%4];" \
        : "=r"(r0), "=r"(r1), "=r"(r2), "=r"(r3) : "r"(a))

__device__ __forceinline__ void mma16816(float c[4], const uint32_t a[4],
                                         uint32_t b0, uint32_t b1) {
    asm volatile(
        "mma.sync.aligned.m16n8k16.row.col.f32.bf16.bf16.f32 "
        "{%0,%1,%2,%3}, {%4,%5,%6,%7}, {%8,%9}, {%0,%1,%2,%3};"
        : "+f"(c[0]), "+f"(c[1]), "+f"(c[2]), "+f"(c[3])
        : "r"(a[0]), "r"(a[1]), "r"(a[2]), "r"(a[3]), "r"(b0), "r"(b1));
}

__device__ __forceinline__ float dec_thr(unsigned hi) {
    return __uint_as_float((hi & 0x80000000u) ? (hi & 0x7FFFFFFFu) : ~hi);
}

// ---------------------------------------------------------------------------
// Kernel 1: transpose coords (c,i,f) -> g_T fp32 + g_Tb bf16, [f][i][c]
// ---------------------------------------------------------------------------
__global__ void k_transpose(const float* __restrict__ coords) {
    __shared__ float s[8][512];
    const int i0 = blockIdx.x * 32, d_base = blockIdx.y * 64;
    const int tid = threadIdx.x;
    const int f = tid & 15, il = tid >> 4, gi = i0 + il;

    for (int d0 = d_base; d0 < d_base + 64; d0 += 8) {
        __syncthreads();
        const int col = i0 * NF + tid;
        #pragma unroll
        for (int dd = 0; dd < 8; dd++)
            s[dd][tid] = (col < F * NF)
                ? coords[(size_t)(d0 + dd) * (F * NF) + col] : 0.f;
        __syncthreads();
        if (gi < F) {
            float t[8];
            #pragma unroll
            for (int dd = 0; dd < 8; dd++) t[dd] = s[dd][il * 16 + f];
            float* dst = g_T + ((size_t)f * F + gi) * D + d0;
            ((float4*)dst)[0] = make_float4(t[0], t[1], t[2], t[3]);
            ((float4*)dst)[1] = make_float4(t[4], t[5], t[6], t[7]);
            __nv_bfloat162 h[4];
            #pragma unroll
            for (int q = 0; q < 4; q++)
                h[q] = __nv_bfloat162(__float2bfloat16_rn(t[2*q]),
                                      __float2bfloat16_rn(t[2*q+1]));
            *(uint4*)(g_Tb + ((size_t)f * F + gi) * D + d0) = *(uint4*)h;
        }
    }
}

// ---------------------------------------------------------------------------
// Kernel 2: sq[f][i]
// ---------------------------------------------------------------------------
__global__ void k_sq() {
    const int row = blockIdx.x * 8 + (threadIdx.x >> 5);
    const int lane = threadIdx.x & 31;
    if (row >= NF * F) return;
    const float4* p = (const float4*)(g_T + (size_t)row * D);
    float s = 0.f;
    #pragma unroll
    for (int q = 0; q < 4; q++) {
        float4 v = p[lane + q * 32];
        s += v.x * v.x + v.y * v.y + v.z * v.z + v.w * v.w;
    }
    #pragma unroll
    for (int o = 16; o; o >>= 1) s += __shfl_xor_sync(FULLM, s, o);
    if (lane == 0) g_sq[row] = s;
}

__global__ void k_dummy() { if (threadIdx.x == 0) g_dummy_sink = 1.0f; }

// ---------------------------------------------------------------------------
// Kernel 3: pure bf16 GEMM -> raw dot products to g_scores
//   grid (16 i-tiles, 16 filters), 256 threads (8 warps, 2m x 4n)
// ---------------------------------------------------------------------------
__global__ void __launch_bounds__(256, 2) k_gemm() {
    extern __shared__ char sm[];
    const uint32_t smb = smem_u32(sm);

    const int tid = threadIdx.x, lane = tid & 31, wid = tid >> 5;
    const int wm = wid & 1, wn = wid >> 1;
    const int f = blockIdx.y, i0 = blockIdx.x * 128;
    const __nv_bfloat16* Tbf = g_Tb + (size_t)f * F * D;

    const int lrow = tid >> 1, lq = tid & 1;
    const int arow_g = min(i0 + lrow, F - 1);
    const uint32_t st_off = (uint32_t)lrow * 80u + (uint32_t)lq * 32u;

    const uint32_t lm_col = (lane & 16) ? 16u : 0u;
    const uint32_t aBase = smb + SM_A + (uint32_t)(wm * 64 + (lane & 15)) * 80u + lm_col;
    const uint32_t bBase = smb + SM_B + (uint32_t)(wn * 32 + (lane & 15)) * 80u + lm_col;

    const __nv_bfloat16* asrc0 = Tbf + (size_t)arow_g * D + lq * 16;
    float* sbase = g_scores + (size_t)(f * FP + i0) * FP;

    for (int jt = 0; jt < 16; jt++) {
        const int jrow_g = min(jt * 128 + lrow, F - 1);
        const __nv_bfloat16* bsrc0 = Tbf + (size_t)jrow_g * D + lq * 16;

        float c[4][4][4];
        #pragma unroll
        for (int mt = 0; mt < 4; mt++)
            #pragma unroll
            for (int nt = 0; nt < 4; nt++)
                #pragma unroll
                for (int e = 0; e < 4; e++) c[mt][nt][e] = 0.f;

        // prologue: prefetch chunks 0,1
        #pragma unroll
        for (int pc = 0; pc < 2; pc++) {
            const uint32_t nb = (uint32_t)pc * BUFB;
            const int ko = pc * 32;
            CP16(smb + SM_A + nb + st_off,       asrc0 + ko);
            CP16(smb + SM_A + nb + st_off + 16u, asrc0 + ko + 8);
            CP16(smb + SM_B + nb + st_off,       bsrc0 + ko);
            CP16(smb + SM_B + nb + st_off + 16u, bsrc0 + ko + 8);
            CP_COMMIT();
        }

        #pragma unroll 1
        for (int kc = 0; kc < 16; kc++) {
            if (kc < 15) CP_WAIT1(); else CP_WAIT0();
            __syncthreads();
            if (kc + 2 < 16) {
                const uint32_t nb = (uint32_t)((kc + 2) % 3) * BUFB;
                const int ko = (kc + 2) * 32;
                CP16(smb + SM_A + nb + st_off,       asrc0 + ko);
                CP16(smb + SM_A + nb + st_off + 16u, asrc0 + ko + 8);
                CP16(smb + SM_B + nb + st_off,       bsrc0 + ko);
                CP16(smb + SM_B + nb + st_off + 16u, bsrc0 + ko + 8);
                CP_COMMIT();
            }
            const uint32_t cb = (uint32_t)(kc % 3) * BUFB;
            #pragma unroll
            for (int ks = 0; ks < 2; ks++) {
                uint32_t a[4][4], b[4][2], t0, t1, t2, t3;
                #pragma unroll
                for (int mt = 0; mt < 4; mt++)
                    LDSM4(a[mt][0], a[mt][1], a[mt][2], a[mt][3],
                          aBase + cb + (uint32_t)mt * 1280u + (uint32_t)ks * 32u);
                #pragma unroll
                for (int p = 0; p < 2; p++) {
                    LDSM4(t0, t1, t2, t3,
                          bBase + cb + (uint32_t)p * 1280u + (uint32_t)ks * 32u);
                    b[2*p][0] = t0; b[2*p][1] = t2;
                    b[2*p+1][0] = t1; b[2*p+1][1] = t3;
                }
                #pragma unroll
                for (int mt = 0; mt < 4; mt++)
                    #pragma unroll
                    for (int nt = 0; nt < 4; nt++)
                        mma16816(c[mt][nt], a[mt], b[nt][0], b[nt][1]);
            }
        }
        __syncthreads();   // ring safety: all reads done before next prologue

        // dump raw dot products (no selection here)
        const int colb = jt * 128 + wn * 32 + 2 * (lane & 3);
        #pragma unroll
        for (int mt = 0; mt < 4; mt++) {
            const int r0 = wm * 64 + mt * 16 + (lane >> 2);
            float* p0 = sbase + (size_t)r0 * FP + colb;
            float* p1 = p0 + (size_t)8 * FP;
            #pragma unroll
            for (int nt = 0; nt < 4; nt++) {
                *(float2*)(p0 + nt * 8) = make_float2(c[mt][nt][0], c[mt][nt][1]);
                *(float2*)(p1 + nt * 8) = make_float2(c[mt][nt][2], c[mt][nt][3]);
            }
        }
    }
}

// ---------------------------------------------------------------------------
// Kernel 4: selection — one warp per (row, filter); top-16 shortlist
// ---------------------------------------------------------------------------
__global__ void __launch_bounds__(256) k_select() {
    const int wid = threadIdx.x >> 5, lane = threadIdx.x & 31;
    const int row = blockIdx.x * 8 + wid;
    if (row >= NF * F) return;
    const int f = row / F, i = row - f * F;
    const float* sc  = g_scores + (size_t)(f * FP + i) * FP;
    const float* sqf = g_sq + f * F;

    unsigned long long Lv = SENT;
    unsigned long long L15 = SENT;
    float thr = __int_as_float(0x7F800000);

    #pragma unroll 1
    for (int it = 0; it < 16; it++) {
        const int j0 = it * 128 + lane * 4;
        float s[4];
        if (j0 < F) {
            const float4 v = *(const float4*)(sc + j0);
            const float4 q = *(const float4*)(sqf + j0);
            s[0] = fmaf(-2.f, v.x, q.x); s[1] = fmaf(-2.f, v.y, q.y);
            s[2] = fmaf(-2.f, v.z, q.z); s[3] = fmaf(-2.f, v.w, q.w);
        } else {
            s[0] = s[1] = s[2] = s[3] = __int_as_float(0x7F800000);
        }
        unsigned pend = (s[0] <= thr ? 1u : 0u) | (s[1] <= thr ? 2u : 0u)
                      | (s[2] <= thr ? 4u : 0u) | (s[3] <= thr ? 8u : 0u);
        while (true) {
            const unsigned any = __ballot_sync(FULLM, pend != 0u);
            if (!any) break;
            const int src = __ffs(any) - 1;
            const unsigned spend = __shfl_sync(FULLM, pend, src);
            const int e = __ffs(spend) - 1;
            if (lane == src) pend &= pend - 1;
            const float vx = (e == 0) ? s[0] : (e == 1) ? s[1]
                           : (e == 2) ? s[2] : s[3];
            const float sv = __shfl_sync(FULLM, vx, src);
            unsigned u = __float_as_uint(sv);
            u ^= ((unsigned)(((int)u) >> 31)) | 0x80000000u;
            const unsigned long long key =
                ((unsigned long long)u << 32)
                | (unsigned)(it * 128 + src * 4 + e);
            if (key < L15) {
                const unsigned bal =
                    __ballot_sync(FULLM, (lane < 16) && (Lv < key));
                const int pos = __popc(bal);
                const unsigned long long up = __shfl_up_sync(FULLM, Lv, 1);
                if (lane < 16)
                    Lv = (lane < pos) ? Lv : ((lane == pos) ? key : up);
                L15 = __shfl_sync(FULLM, Lv, 15);
                thr = dec_thr((unsigned)(L15 >> 32));
                pend &= (s[0] <= thr ? 1u : 0u) | (s[1] <= thr ? 2u : 0u)
                      | (s[2] <= thr ? 4u : 0u) | (s[3] <= thr ? 8u : 0u);
            }
        }
    }
    if (lane < 16)
        g_cand[row * SL + lane] = (int)(unsigned)(Lv & 0xFFFFFFFFull);
}

// ---------------------------------------------------------------------------
// Kernel 5: exact fp32 rescore of the shortlist; emit top-8 indices
// ---------------------------------------------------------------------------
__global__ void __launch_bounds__(256) k_rescore() {
    const int wid = threadIdx.x >> 5, lane = threadIdx.x & 31;
    const int row = blockIdx.x * 8 + wid;
    if (row >= NF * F) return;
    const int f = row / F, i = row - f * F;
    const float* xi = g_T + (size_t)row * D;
    float4 xa[4];
    #pragma unroll
    for (int q = 0; q < 4; q++) xa[q] = *(const float4*)(xi + lane * 16 + q * 4);

    unsigned long long keys[SL];
    #pragma unroll 1
    for (int c = 0; c < SL; c += 2) {
        const int j0 = g_cand[row * SL + c];
        const int j1 = g_cand[row * SL + c + 1];
        const float* x0 = g_T + ((size_t)f * F + j0) * D;
        const float* x1 = g_T + ((size_t)f * F + j1) * D;
        float p0 = 0.f, p1 = 0.f;
        #pragma unroll
        for (int q = 0; q < 4; q++) {
            float4 a = xa[q];
            float4 v0 = *(const float4*)(x0 + lane * 16 + q * 4);
            float4 v1 = *(const float4*)(x1 + lane * 16 + q * 4);
            p0 = fmaf(a.x, v0.x, p0); p1 = fmaf(a.x, v1.x, p1);
            p0 = fmaf(a.y, v0.y, p0); p1 = fmaf(a.y, v1.y, p1);
            p0 = fmaf(a.z, v0.z, p0); p1 = fmaf(a.z, v1.z, p1);
            p0 = fmaf(a.w, v0.w, p0); p1 = fmaf(a.w, v1.w, p1);
        }
        #pragma unroll
        for (int o = 16; o; o >>= 1) {
            p0 += __shfl_xor_sync(FULLM, p0, o);
            p1 += __shfl_xor_sync(FULLM, p1, o);
        }
        const float s0 = fmaf(-2.f, p0, g_sq[f * F + j0]);
        const float s1 = fmaf(-2.f, p1, g_sq[f * F + j1]);
        unsigned u0 = __float_as_uint(s0);
        u0 ^= ((unsigned)(((int)u0) >> 31)) | 0x80000000u;
        unsigned u1 = __float_as_uint(s1);
        u1 ^= ((unsigned)(((int)u1) >> 31)) | 0x80000000u;
        keys[c]     = ((unsigned long long)u0 << 32) | (unsigned)j0;
        keys[c + 1] = ((unsigned long long)u1 << 32) | (unsigned)j1;
    }
    if (lane == 0) {
        #pragma unroll
        for (int k = 0; k < KNN; k++) {
            int m = k;
            #pragma unroll
            for (int c = k + 1; c < SL; c++) if (keys[c] < keys[m]) m = c;
            const unsigned long long tk = keys[m];
            keys[m] = keys[k]; keys[k] = tk;
            g_idx[((size_t)i * KNN + k) * NF + f] =
                (int)(unsigned)(tk & 0xFFFFFFFFull);
        }
    }
}

// ---------------------------------------------------------------------------
// Kernel 6: gather — warp covers 32 contiguous (ik,f) pairs
// ---------------------------------------------------------------------------
__global__ void k_gather(const float* __restrict__ inp, float* __restrict__ out) {
    const int wid = threadIdx.x >> 5, lane = threadIdx.x & 31;
    const int ik = blockIdx.x * 16 + wid * 2 + (lane >> 4);
    const int f  = lane & 15;
    const int j  = g_idx[ik * NF + f];
    const float* src = inp + (size_t)j * NF + f;
    float* dst = out + (size_t)ik * NF + f;
    #pragma unroll 8
    for (int b = 0; b < 64; b++)
        dst[(size_t)b * (F * KNN * NF)] = src[(size_t)b * (F * NF)];
}

// ---------------------------------------------------------------------------
extern "C" void kernel_launch(void* const* d_in, const int* in_sizes, int n_in,
                              void* d_out, int out_size) {
    const float* inputs = (const float*)d_in[0];
    const float* coords = (const float*)d_in[1];
    if (n_in >= 2 && in_sizes[0] == D * F * NF) {
        const float* t = inputs; inputs = coords; coords = t;
    }
    (void)out_size;

    static bool attr_done = false;
    if (!attr_done) {
        cudaFuncSetAttribute(k_gemm,
            cudaFuncAttributeMaxDynamicSharedMemorySize, SM_TOTAL);
        attr_done = true;
    }

    k_transpose<<<dim3((F + 31) / 32, D / 64), 512>>>(coords);
    k_sq<<<(NF * F + 7) / 8, 256>>>();
    k_dummy<<<1, 32>>>();
    k_gemm<<<dim3(16, NF), 256, SM_TOTAL>>>();
    k_select<<<(NF * F + 7) / 8, 256>>>();
    k_rescore<<<(NF * F + 7) / 8, 256>>>();
    k_gather<<<F * KNN / 16, 256>>>(inputs, (float*)d_out);
}